// round 7
// baseline (speedup 1.0000x reference)
#include <cuda_runtime.h>
#include <math.h>

// ---- persistent device state (no allocations allowed) ----
// fp32-bit log-binning: bin = float_bits(d) >> 17 (64 bins/octave).
// d < 16 => bin <= 8383; 8448 with clamp.
#define NBINS  8448
__device__ unsigned g_hist[NBINS];   // zero at load; reset by pass2 each replay
__device__ double   g_sum_d;
__device__ double   g_sum_d2;

#define P1_BLOCKS  1184              // 8 CTAs/SM target
#define P1_THREADS 256
#define P1_WARPS   (P1_THREADS / 32)

#define P2_THREADS 1024
#define P2_WARPS   (P2_THREADS / 32)

__device__ __forceinline__ float warp_reduce_f(float v) {
    #pragma unroll
    for (int o = 16; o > 0; o >>= 1)
        v += __shfl_xor_sync(0xFFFFFFFFu, v, o);
    return v;
}

// 1 - erf(x), x >= 0. Abramowitz & Stegun 7.1.26, |err| <= 1.5e-7.
__device__ __forceinline__ float one_minus_erf(float x) {
    float t = __fdividef(1.0f, fmaf(0.3275911f, x, 1.0f));
    float poly = fmaf(t, 1.061405429f, -1.453152027f);
    poly = fmaf(poly, t, 1.421413741f);
    poly = fmaf(poly, t, -0.284496736f);
    poly = fmaf(poly, t, 0.254829592f);
    poly *= t;
    return poly * __expf(-x * x);
}

// =========================== pass 1 ==========================================
__global__ __launch_bounds__(P1_THREADS)
void afl_pass1_kernel(const float* __restrict__ pred,
                      const float* __restrict__ target,
                      long long n) {
    __shared__ unsigned s_hist[NBINS];
    const int tid = threadIdx.x;

    for (int b = tid; b < NBINS; b += P1_THREADS) s_hist[b] = 0u;
    __syncthreads();

    const long long n4 = n >> 2;
    const float4* __restrict__ p4 = (const float4*)pred;
    const float4* __restrict__ t4 = (const float4*)target;
    const long long stride = (long long)gridDim.x * P1_THREADS;

    float sd = 0.0f, sd2 = 0.0f;
    long long i = (long long)blockIdx.x * P1_THREADS + tid;

    for (; i + 3LL * stride < n4; i += 4LL * stride) {
        float4 av[4], bv[4];
        #pragma unroll
        for (int u = 0; u < 4; u++) av[u] = __ldcs(&p4[i + (long long)u * stride]);
        #pragma unroll
        for (int u = 0; u < 4; u++) bv[u] = __ldcs(&t4[i + (long long)u * stride]);
        #pragma unroll
        for (int u = 0; u < 4; u++) {
            float d0 = fabsf(av[u].x - bv[u].x);
            float d1 = fabsf(av[u].y - bv[u].y);
            float d2 = fabsf(av[u].z - bv[u].z);
            float d3 = fabsf(av[u].w - bv[u].w);
            sd  += (d0 + d1) + (d2 + d3);
            sd2 += fmaf(d0, d0, d1 * d1) + fmaf(d2, d2, d3 * d3);
            atomicAdd(&s_hist[min(__float_as_uint(d0) >> 17, NBINS - 1u)], 1u);
            atomicAdd(&s_hist[min(__float_as_uint(d1) >> 17, NBINS - 1u)], 1u);
            atomicAdd(&s_hist[min(__float_as_uint(d2) >> 17, NBINS - 1u)], 1u);
            atomicAdd(&s_hist[min(__float_as_uint(d3) >> 17, NBINS - 1u)], 1u);
        }
    }
    for (; i < n4; i += stride) {
        float4 a = __ldcs(&p4[i]);
        float4 b = __ldcs(&t4[i]);
        float d0 = fabsf(a.x - b.x);
        float d1 = fabsf(a.y - b.y);
        float d2 = fabsf(a.z - b.z);
        float d3 = fabsf(a.w - b.w);
        sd  += (d0 + d1) + (d2 + d3);
        sd2 += fmaf(d0, d0, d1 * d1) + fmaf(d2, d2, d3 * d3);
        atomicAdd(&s_hist[min(__float_as_uint(d0) >> 17, NBINS - 1u)], 1u);
        atomicAdd(&s_hist[min(__float_as_uint(d1) >> 17, NBINS - 1u)], 1u);
        atomicAdd(&s_hist[min(__float_as_uint(d2) >> 17, NBINS - 1u)], 1u);
        atomicAdd(&s_hist[min(__float_as_uint(d3) >> 17, NBINS - 1u)], 1u);
    }
    for (long long j = (n4 << 2) + (long long)blockIdx.x * P1_THREADS + tid;
         j < n; j += stride) {                     // n%4 tail
        float d = fabsf(pred[j] - target[j]);
        sd += d; sd2 += d * d;
        atomicAdd(&s_hist[min(__float_as_uint(d) >> 17, NBINS - 1u)], 1u);
    }

    // block reduce sums -> global double accumulators
    sd  = warp_reduce_f(sd);
    sd2 = warp_reduce_f(sd2);
    __shared__ double shA[P1_WARPS];
    __shared__ double shB[P1_WARPS];
    int lane = tid & 31;
    int wid  = tid >> 5;
    if (lane == 0) { shA[wid] = (double)sd; shB[wid] = (double)sd2; }
    __syncthreads();
    if (wid == 0) {
        double a = (lane < P1_WARPS) ? shA[lane] : 0.0;
        double b = (lane < P1_WARPS) ? shB[lane] : 0.0;
        #pragma unroll
        for (int o = 4; o > 0; o >>= 1) {
            a += __shfl_xor_sync(0xFFFFFFFFu, a, o);
            b += __shfl_xor_sync(0xFFFFFFFFu, b, o);
        }
        if (lane == 0) { atomicAdd(&g_sum_d, a); atomicAdd(&g_sum_d2, b); }
    }
    __syncthreads();

    // flush block histogram to global (only populated bins)
    for (int b = tid; b < NBINS; b += P1_THREADS) {
        unsigned v = s_hist[b];
        if (v) atomicAdd(&g_hist[b], v);
    }
}

// =========================== pass 2 + finalize ==============================
__global__ __launch_bounds__(P2_THREADS)
void afl_pass2_kernel(float* __restrict__ out, long long n) {
    const int tid = threadIdx.x;

    const double sdt  = g_sum_d;
    const double sd2t = g_sum_d2;
    const double dn   = (double)n;
    const double var  = (sd2t - sdt * sdt / dn) / (dn - 1.0);
    const float  c    = (float)(0.7071067811865476 / var);

    // evaluate erf at each populated bin's bit-midpoint; reset hist as we go
    float sp = 0.0f;
    for (int b = tid; b < NBINS; b += P2_THREADS) {
        unsigned cnt = g_hist[b];
        if (cnt) {
            g_hist[b] = 0u;   // reset for next replay
            float rep = __uint_as_float(((unsigned)b << 17) | 0x10000u);
            sp += (float)cnt * one_minus_erf(rep * c);
        }
    }

    sp = warp_reduce_f(sp);
    __shared__ double shC[P2_WARPS];
    __shared__ double s_total;
    int lane = tid & 31;
    int wid  = tid >> 5;
    if (lane == 0) shC[wid] = (double)sp;
    __syncthreads();
    if (wid == 0) {
        double a = (lane < P2_WARPS) ? shC[lane] : 0.0;
        #pragma unroll
        for (int o = 16; o > 0; o >>= 1)
            a += __shfl_xor_sync(0xFFFFFFFFu, a, o);
        if (lane == 0) s_total = a;
    }
    __syncthreads();

    if (tid == 0) {
        double mean_d = sdt / dn;
        float  p      = (float)(s_total / dn);
        float  gamma  = -logf(p);
        float  pw     = expf(gamma * log1pf(-p));   // (1-p)^gamma
        out[0] = (float)mean_d * pw + log1pf((float)var);
        // reset sums for next graph replay
        g_sum_d = 0.0; g_sum_d2 = 0.0;
    }
}

// ================================ launcher ==================================
extern "C" void kernel_launch(void* const* d_in, const int* in_sizes, int n_in,
                              void* d_out, int out_size) {
    const float* pred   = (const float*)d_in[0];
    const float* target = (const float*)d_in[1];
    float* out = (float*)d_out;
    long long n = (long long)in_sizes[0];

    afl_pass1_kernel<<<P1_BLOCKS, P1_THREADS>>>(pred, target, n);
    afl_pass2_kernel<<<1, P2_THREADS>>>(out, n);
}

// round 8
// speedup vs baseline: 1.2589x; 1.2589x over previous
#include <cuda_runtime.h>
#include <math.h>

// ---- persistent device state (no allocations allowed) ----
__device__ double   g_sum_d;
__device__ double   g_sum_d2;
__device__ double   g_sum_p;
__device__ unsigned g_count;    // barrier arrive counter
__device__ unsigned g_gen;      // barrier generation (monotonic across replays)

#define NTHR   256
#define NWARPS (NTHR / 32)
#define MAX_CTA_PER_SM 4

// fp32-bit log-binning: bin = float_bits(d) >> 17 (64 bins/octave).
// d < 16 => bin <= 8383; 8448 with clamp.
#define NBINS  8448

__device__ __forceinline__ float warp_reduce_f(float v) {
    #pragma unroll
    for (int o = 16; o > 0; o >>= 1)
        v += __shfl_xor_sync(0xFFFFFFFFu, v, o);
    return v;
}

// 1 - erf(x), x >= 0. Abramowitz & Stegun 7.1.26, |err| <= 1.5e-7.
__device__ __forceinline__ float one_minus_erf(float x) {
    float t = __fdividef(1.0f, fmaf(0.3275911f, x, 1.0f));
    float poly = fmaf(t, 1.061405429f, -1.453152027f);
    poly = fmaf(poly, t, 1.421413741f);
    poly = fmaf(poly, t, -0.284496736f);
    poly = fmaf(poly, t, 0.254829592f);
    poly *= t;
    return poly * __expf(-x * x);
}

// Sense-reversing grid barrier; requires all blocks co-resident.
__device__ __forceinline__ void grid_barrier(unsigned nblocks) {
    __syncthreads();
    if (threadIdx.x == 0) {
        unsigned gen = *((volatile unsigned*)&g_gen);
        __threadfence();
        unsigned arrived = atomicAdd(&g_count, 1u);
        if (arrived == nblocks - 1) {
            g_count = 0;
            __threadfence();
            atomicAdd(&g_gen, 1u);
        } else {
            while (*((volatile unsigned*)&g_gen) == gen) { }
            __threadfence();
        }
    }
    __syncthreads();
}

// ============================ fused persistent kernel =======================
__global__ __launch_bounds__(NTHR, MAX_CTA_PER_SM)
void afl_fused_kernel(const float* __restrict__ pred,
                      const float* __restrict__ target,
                      float* __restrict__ out,
                      long long n) {
    __shared__ unsigned s_hist[NBINS];
    __shared__ double   shA[NWARPS];
    __shared__ double   shB[NWARPS];

    const int tid = threadIdx.x;
    const int bid = blockIdx.x;

    for (int b = tid; b < NBINS; b += NTHR) s_hist[b] = 0u;
    __syncthreads();

    const long long n4 = n >> 2;
    const float4* __restrict__ p4 = (const float4*)pred;
    const float4* __restrict__ t4 = (const float4*)target;
    const long long stride = (long long)gridDim.x * NTHR;

    // -------- pass 1: sums + private SMEM histogram --------
    float sd = 0.0f, sd2 = 0.0f;
    long long i = (long long)bid * NTHR + tid;
    for (; i + 3LL * stride < n4; i += 4LL * stride) {
        float4 av[4], bv[4];
        #pragma unroll
        for (int u = 0; u < 4; u++) av[u] = __ldcs(&p4[i + (long long)u * stride]);
        #pragma unroll
        for (int u = 0; u < 4; u++) bv[u] = __ldcs(&t4[i + (long long)u * stride]);
        #pragma unroll
        for (int u = 0; u < 4; u++) {
            float d0 = fabsf(av[u].x - bv[u].x);
            float d1 = fabsf(av[u].y - bv[u].y);
            float d2 = fabsf(av[u].z - bv[u].z);
            float d3 = fabsf(av[u].w - bv[u].w);
            sd  += (d0 + d1) + (d2 + d3);
            sd2 += fmaf(d0, d0, d1 * d1) + fmaf(d2, d2, d3 * d3);
            atomicAdd(&s_hist[min(__float_as_uint(d0) >> 17, NBINS - 1u)], 1u);
            atomicAdd(&s_hist[min(__float_as_uint(d1) >> 17, NBINS - 1u)], 1u);
            atomicAdd(&s_hist[min(__float_as_uint(d2) >> 17, NBINS - 1u)], 1u);
            atomicAdd(&s_hist[min(__float_as_uint(d3) >> 17, NBINS - 1u)], 1u);
        }
    }
    for (; i < n4; i += stride) {
        float4 a = __ldcs(&p4[i]);
        float4 b = __ldcs(&t4[i]);
        float d0 = fabsf(a.x - b.x);
        float d1 = fabsf(a.y - b.y);
        float d2 = fabsf(a.z - b.z);
        float d3 = fabsf(a.w - b.w);
        sd  += (d0 + d1) + (d2 + d3);
        sd2 += fmaf(d0, d0, d1 * d1) + fmaf(d2, d2, d3 * d3);
        atomicAdd(&s_hist[min(__float_as_uint(d0) >> 17, NBINS - 1u)], 1u);
        atomicAdd(&s_hist[min(__float_as_uint(d1) >> 17, NBINS - 1u)], 1u);
        atomicAdd(&s_hist[min(__float_as_uint(d2) >> 17, NBINS - 1u)], 1u);
        atomicAdd(&s_hist[min(__float_as_uint(d3) >> 17, NBINS - 1u)], 1u);
    }
    for (long long j = (n4 << 2) + (long long)bid * NTHR + tid;
         j < n; j += stride) {                    // n%4 tail
        float d = fabsf(pred[j] - target[j]);
        sd += d; sd2 += d * d;
        atomicAdd(&s_hist[min(__float_as_uint(d) >> 17, NBINS - 1u)], 1u);
    }

    // block reduce sums -> global double accumulators
    sd  = warp_reduce_f(sd);
    sd2 = warp_reduce_f(sd2);
    int lane = tid & 31;
    int wid  = tid >> 5;
    if (lane == 0) { shA[wid] = (double)sd; shB[wid] = (double)sd2; }
    __syncthreads();
    if (wid == 0) {
        double a = (lane < NWARPS) ? shA[lane] : 0.0;
        double b = (lane < NWARPS) ? shB[lane] : 0.0;
        #pragma unroll
        for (int o = 4; o > 0; o >>= 1) {
            a += __shfl_xor_sync(0xFFFFFFFFu, a, o);
            b += __shfl_xor_sync(0xFFFFFFFFu, b, o);
        }
        if (lane == 0) { atomicAdd(&g_sum_d, a); atomicAdd(&g_sum_d2, b); }
    }
    __threadfence();
    grid_barrier(gridDim.x);

    // -------- var now global-complete --------
    const double sdt  = g_sum_d;
    const double sd2t = g_sum_d2;
    const double dn   = (double)n;
    const double var  = (sd2t - sdt * sdt / dn) / (dn - 1.0);
    const float  c    = (float)(0.7071067811865476 / var);

    // -------- local bin-eval: erf once per populated bin of OWN hist --------
    float sp = 0.0f;
    for (int b = tid; b < NBINS; b += NTHR) {
        unsigned cnt = s_hist[b];
        if (cnt) {
            float rep = __uint_as_float(((unsigned)b << 17) | 0x10000u);
            sp += (float)cnt * one_minus_erf(rep * c);
        }
    }
    sp = warp_reduce_f(sp);
    if (lane == 0) shA[wid] = (double)sp;
    __syncthreads();
    if (wid == 0) {
        double a = (lane < NWARPS) ? shA[lane] : 0.0;
        #pragma unroll
        for (int o = 4; o > 0; o >>= 1)
            a += __shfl_xor_sync(0xFFFFFFFFu, a, o);
        if (lane == 0) atomicAdd(&g_sum_p, a);
    }

    // -------- phase-2 arrive; block 0 finalizes --------
    __syncthreads();
    __threadfence();
    if (tid == 0) {
        if (bid != 0) {
            atomicAdd(&g_count, 1u);
        } else {
            const unsigned need = gridDim.x - 1;
            while (*((volatile unsigned*)&g_count) != need) { }
            g_count = 0;
            __threadfence();
            double mean_d = sdt / dn;
            float  p      = (float)(g_sum_p / dn);
            float  gamma  = -logf(p);
            float  pw     = expf(gamma * log1pf(-p));   // (1-p)^gamma
            out[0] = (float)mean_d * pw + log1pf((float)var);
            g_sum_d = 0.0; g_sum_d2 = 0.0; g_sum_p = 0.0;
        }
    }
}

// ================================ launcher ==================================
extern "C" void kernel_launch(void* const* d_in, const int* in_sizes, int n_in,
                              void* d_out, int out_size) {
    const float* pred   = (const float*)d_in[0];
    const float* target = (const float*)d_in[1];
    float* out = (float*)d_out;
    long long n = (long long)in_sizes[0];

    // Guaranteed-co-resident grid: SMs * achievable CTAs/SM (barrier safety).
    int dev = 0, nsm = 148;
    cudaGetDevice(&dev);
    cudaDeviceGetAttribute(&nsm, cudaDevAttrMultiProcessorCount, dev);
    int per_sm = 0;
    cudaOccupancyMaxActiveBlocksPerMultiprocessor(&per_sm, afl_fused_kernel,
                                                  NTHR, 0);
    if (per_sm < 1) per_sm = 1;
    if (per_sm > MAX_CTA_PER_SM) per_sm = MAX_CTA_PER_SM;
    int grid = nsm * per_sm;

    afl_fused_kernel<<<grid, NTHR>>>(pred, target, out, n);
}